// round 17
// baseline (speedup 1.0000x reference)
#include <cuda_runtime.h>
#include <cuda_fp16.h>
#include <cstddef>
#include <cstdint>

// Problem constants (B=16, T=2048, D=256, WINDOW=128)
#define BB 16
#define TT 2048
#define DD 256
#define WIN 128
#define BT (BB*TT)          // 32768
#define PADT 2432

// ---------------- scratch (__device__ globals; no allocation) ---------------
__device__ float g_q[(size_t)BT * 256];          // raw q, row-major
__device__ float g_cwP[(size_t)16 * 12 * 4096];  // band A, packed fragment order
__device__ float g_uek[(size_t)BB * PADT * 512]; // interleaved [b][s+128][(u,ek) x 256d]
__device__ float g_Spart[(size_t)512 * 512];     // [mblk*2+wm][(su,se) x 256d]
__device__ float g_S[(size_t)BB * 512];          // [b][(Su,Se) x 256d]

__device__ __half g_xh[(size_t)BT * 256];        // x fp16, packed fragment order
__device__ __half g_wqkvh[(size_t)256 * 768];    // fp16 W: q | interleaved (k,v)
__device__ float g_yp[(size_t)BT * 256];         // y, packed tf32 fragment order
__device__ float g_wo[(size_t)256 * 256];        // packed tf32 Wo

// ---------------- helpers ---------------------------------------------------
__device__ __forceinline__ float to_tf32(float v) {
    float r;
    asm("cvt.rna.tf32.f32 %0, %1;" : "=f"(r) : "f"(v));
    return r;
}
__device__ __forceinline__ uint32_t smem_u32(const void* p) {
    return (uint32_t)__cvta_generic_to_shared(p);
}
__device__ __forceinline__ uint32_t h2pack(float lo, float hi) {
    __half2 h = __floats2half2_rn(lo, hi);
    return *(uint32_t*)&h;
}
#define CP16(dst, src) \
    asm volatile("cp.async.cg.shared.global [%0], [%1], 16;" :: "r"(dst), "l"(src))

// ---------------- fp16 operand packing --------------------------------------
// A fp16 packed: region(mblk, kc 0..7) = 4096 halves (128 m x 32 k).
// slot = kk*8+mi (kk 0..1), per lane one uint4 = A-fragment
// {A[r][c],A[r][c+1]},{A[r+8][c],A[r+8][c+1]},{A[r][c+8],..},{A[r+8][c+8],..}
// r = mblk*128+mi*16+quad, c = kc*32+kk*16+qt*2.
__global__ void pack_ah(const float* __restrict__ src)
{
    int fid = blockIdx.x * 256 + threadIdx.x;     // uint4 id, 1048576 total
    int rg = fid >> 9;
    int q  = fid & 511;
    int slot = q >> 5;
    int lane = q & 31;
    int mblk = rg >> 3, kc = rg & 7;
    int kk = slot >> 3, mi = slot & 7;
    int quad = lane >> 2, qt = lane & 3;
    int r0 = mblk * 128 + mi * 16 + quad;
    int c0 = kc * 32 + kk * 16 + qt * 2;
    const float* s = src + (size_t)r0 * 256 + c0;
    float2 p00 = *(const float2*)(s);
    float2 p80 = *(const float2*)(s + 8 * 256);
    float2 p08 = *(const float2*)(s + 8);
    float2 p88 = *(const float2*)(s + 8 * 256 + 8);
    uint4 v;
    v.x = h2pack(p00.x, p00.y);
    v.y = h2pack(p80.x, p80.y);
    v.z = h2pack(p08.x, p08.y);
    v.w = h2pack(p88.x, p88.y);
    *(uint4*)&g_xh[(size_t)fid * 8] = v;
}

// B fp16 packed: region(nblk 0..5, kc 0..7) = 4096 halves (128 n x 32 k).
// slot = kk*16+nj, per lane one uint2 = B-fragment
// {W[k0][n],W[k0+1][n]},{W[k0+8][n],W[k0+9][n]},
// k0 = kc*32+kk*16+qt*2, n = nblk*128+nj*8+quad.
// Column map: n<256 -> Wq_n; else even -> Wk_{(n-256)/2}, odd -> Wv.
__global__ void pack_wh(const float* __restrict__ Wq, const float* __restrict__ Wk,
                        const float* __restrict__ Wv)
{
    int fid = blockIdx.x * 256 + threadIdx.x;     // uint2 id, 49152 total
    int rg = fid >> 10;
    int q  = fid & 1023;
    int slot = q >> 5;
    int lane = q & 31;
    int nblk = rg >> 3, kc = rg & 7;
    int kk = slot >> 4, nj = slot & 15;
    int quad = lane >> 2, qt = lane & 3;
    int k0 = kc * 32 + kk * 16 + qt * 2;
    int n = nblk * 128 + nj * 8 + quad;
    const float* W; int nn;
    if (n < 256) { W = Wq; nn = n; }
    else { int np = n - 256; W = (np & 1) ? Wv : Wk; nn = np >> 1; }
    float v0 = W[(size_t)k0 * 256 + nn];
    float v1 = W[(size_t)(k0 + 1) * 256 + nn];
    float v8 = W[(size_t)(k0 + 8) * 256 + nn];
    float v9 = W[(size_t)(k0 + 9) * 256 + nn];
    uint2 v;
    v.x = h2pack(v0, v1);
    v.y = h2pack(v8, v9);
    *(uint2*)&g_wqkvh[(size_t)fid * 4] = v;
}

// Wo packed tf32 (output GEMM stays tf32): region(nblk 0..1, kc 0..7)
__global__ void pack_wo(const float* __restrict__ Wo)
{
    int base = blockIdx.x * 256 + threadIdx.x;    // float2 id, 32768 total
    int rg = base >> 11;
    int q  = base & 2047;
    int slot = q >> 5;
    int lane = q & 31;
    int nblk = rg >> 3, kc = rg & 7;
    int kk = slot >> 4, nj = slot & 15;
    int quad = lane >> 2, qt = lane & 3;
    int k0 = kc * 32 + kk * 8 + qt;
    int n = nblk * 128 + nj * 8 + quad;
    float v0 = Wo[(size_t)k0 * 256 + n];
    float v1 = Wo[(size_t)(k0 + 4) * 256 + n];
    *(float2*)&g_wo[(size_t)base * 2] = make_float2(to_tf32(v0), to_tf32(v1));
}

// ---------------- mma macros ------------------------------------------------
#define MMA_F16(d, a, b) \
    asm volatile("mma.sync.aligned.m16n8k16.row.col.f32.f16.f16.f32 " \
                 "{%0,%1,%2,%3},{%4,%5,%6,%7},{%8,%9},{%0,%1,%2,%3};" \
                 : "+f"(d[0]), "+f"(d[1]), "+f"(d[2]), "+f"(d[3]) \
                 : "r"(a.x), "r"(a.y), "r"(a.z), "r"(a.w), "r"(b.x), "r"(b.y))

#define MMA_TF32V(d, a, b) \
    asm volatile("mma.sync.aligned.m16n8k8.row.col.f32.tf32.tf32.f32 " \
                 "{%0,%1,%2,%3},{%4,%5,%6,%7},{%8,%9},{%0,%1,%2,%3};" \
                 : "+f"(d[0]), "+f"(d[1]), "+f"(d[2]), "+f"(d[3]) \
                 : "r"(a.x), "r"(a.y), "r"(a.z), "r"(a.w), "r"(b.x), "r"(b.y))

#define MMA_TF32S(d, a, b0, b1) \
    asm volatile("mma.sync.aligned.m16n8k8.row.col.f32.tf32.tf32.f32 " \
                 "{%0,%1,%2,%3},{%4,%5,%6,%7},{%8,%9},{%0,%1,%2,%3};" \
                 : "+f"(d[0]), "+f"(d[1]), "+f"(d[2]), "+f"(d[3]) \
                 : "r"(a.x), "r"(a.y), "r"(a.z), "r"(a.w), "r"(b0), "r"(b1))

// ---------------- QKV GEMM: fp16 k16, fused elementwise epilogue ------------
#define QH_SMEM (2 * 1024 * 16)    // 2 stages x (512 A + 512 B) uint4

__global__ void __launch_bounds__(256, 2) gemm_qkv_h()
{
    extern __shared__ uint4 sm16[];
    const int tid = threadIdx.x;
    const int nblk = blockIdx.x;     // 0..5
    const int mblk = blockIdx.y;     // 0..255
    const uint4* Abase = (const uint4*)g_xh + (size_t)mblk * 8 * 512;
    const uint4* Bbase = (const uint4*)g_wqkvh + (size_t)nblk * 8 * 512;
    const int lane = tid & 31, w = tid >> 5;
    const int wm = w & 1, wn = w >> 1;
    const int quad = lane >> 2, qt = lane & 3;

    float acc[4][4][4];
#pragma unroll
    for (int i = 0; i < 4; i++)
#pragma unroll
        for (int j = 0; j < 4; j++)
#pragma unroll
            for (int e = 0; e < 4; e++) acc[i][j][e] = 0.f;

    {
        uint4* dA = sm16; uint4* dB = sm16 + 512;
#pragma unroll
        for (int r = 0; r < 2; r++) {
            CP16(smem_u32(dA + r * 256 + tid), Abase + r * 256 + tid);
            CP16(smem_u32(dB + r * 256 + tid), Bbase + r * 256 + tid);
        }
        asm volatile("cp.async.commit_group;");
    }
    int stage = 0;
    for (int c = 0; c < 8; c++) {
        if (c < 7) {
            uint4* dA = sm16 + (stage ^ 1) * 1024;
            uint4* dB = dA + 512;
            const uint4* gA = Abase + (size_t)(c + 1) * 512;
            const uint4* gB = Bbase + (size_t)(c + 1) * 512;
#pragma unroll
            for (int r = 0; r < 2; r++) {
                CP16(smem_u32(dA + r * 256 + tid), gA + r * 256 + tid);
                CP16(smem_u32(dB + r * 256 + tid), gB + r * 256 + tid);
            }
            asm volatile("cp.async.commit_group;");
            asm volatile("cp.async.wait_group 1;");
        } else {
            asm volatile("cp.async.wait_group 0;");
        }
        __syncthreads();

        const uint4* A = sm16 + stage * 1024;
        const uint2* B2 = (const uint2*)(A + 512);
#pragma unroll
        for (int kk = 0; kk < 2; kk++) {
            uint4 af[4];
            uint2 bf[4];
#pragma unroll
            for (int i = 0; i < 4; i++)
                af[i] = A[(kk * 8 + wm * 4 + i) * 32 + lane];
#pragma unroll
            for (int j = 0; j < 4; j++)
                bf[j] = B2[(kk * 16 + wn * 4 + j) * 32 + lane];
#pragma unroll
            for (int i = 0; i < 4; i++)
#pragma unroll
                for (int j = 0; j < 4; j++) MMA_F16(acc[i][j], af[i], bf[j]);
        }
        __syncthreads();
        stage ^= 1;
    }

    if (nblk < 2) {
        // q columns: store raw q row-major
#pragma unroll
        for (int i = 0; i < 4; i++) {
#pragma unroll
            for (int j = 0; j < 4; j++) {
                int r = mblk * 128 + wm * 64 + i * 16 + quad;
                int cc = nblk * 128 + wn * 32 + j * 8 + qt * 2;
                *(float2*)&g_q[(size_t)r * 256 + cc] = make_float2(acc[i][j][0], acc[i][j][1]);
                *(float2*)&g_q[(size_t)(r + 8) * 256 + cc] = make_float2(acc[i][j][2], acc[i][j][3]);
            }
        }
    } else {
        // interleaved (k,v): ek/u, uek write, per-(b,d) partial sums
        const int b = mblk >> 4;
        const int trow0 = (mblk & 15) * 128 + wm * 64;
        float su[4] = {0.f, 0.f, 0.f, 0.f};
        float se[4] = {0.f, 0.f, 0.f, 0.f};
#pragma unroll
        for (int i = 0; i < 4; i++) {
            int t = trow0 + i * 16 + quad;
            size_t ur = ((size_t)b * PADT + t + 128) * 512;
#pragma unroll
            for (int j = 0; j < 4; j++) {
                int d = (nblk - 2) * 64 + wn * 16 + j * 4 + qt;
                float ek0 = expf(acc[i][j][0]);
                float u0  = ek0 * acc[i][j][1];
                float ek8 = expf(acc[i][j][2]);
                float u8  = ek8 * acc[i][j][3];
                *(float2*)&g_uek[ur + 2 * d] =
                    make_float2(to_tf32(u0), to_tf32(ek0));
                *(float2*)&g_uek[ur + 8 * 512 + 2 * d] =
                    make_float2(to_tf32(u8), to_tf32(ek8));
                su[j] += u0 + u8;
                se[j] += ek0 + ek8;
            }
        }
#pragma unroll
        for (int off = 4; off < 32; off <<= 1) {
#pragma unroll
            for (int j = 0; j < 4; j++) {
                su[j] += __shfl_xor_sync(0xffffffffu, su[j], off);
                se[j] += __shfl_xor_sync(0xffffffffu, se[j], off);
            }
        }
        if (quad == 0) {
#pragma unroll
            for (int j = 0; j < 4; j++) {
                int d = (nblk - 2) * 64 + wn * 16 + j * 4 + qt;
                size_t s = ((size_t)mblk * 2 + wm) * 512 + 2 * d;
                g_Spart[s]     = su[j];
                g_Spart[s + 1] = se[j];
            }
        }
    }
}

// ---------------- output projection: packed tf32 GEMM -----------------------
#define PG_SMEM (2 * 8192 * 4)

__global__ void __launch_bounds__(256, 2) gemm_tf32p(
    const float* __restrict__ Ap, const float* __restrict__ Bp,
    float* __restrict__ C, int ldc)
{
    extern __shared__ float sm[];
    const int tid = threadIdx.x;
    const int nblk = blockIdx.x;
    const int mblk = blockIdx.y;
    const float* Abase = Ap + (size_t)mblk * 8 * 4096;
    const float* Bbase = Bp + (size_t)nblk * 8 * 4096;
    const int lane = tid & 31, w = tid >> 5;
    const int wm = w & 1, wn = w >> 1;
    const int quad = lane >> 2, qt = lane & 3;

    float acc[4][4][4];
#pragma unroll
    for (int i = 0; i < 4; i++)
#pragma unroll
        for (int j = 0; j < 4; j++)
#pragma unroll
            for (int e = 0; e < 4; e++) acc[i][j][e] = 0.f;

    {
        float* dA = sm; float* dB = sm + 4096;
#pragma unroll
        for (int r = 0; r < 4; r++) {
            CP16(smem_u32(dA + (r * 256 + tid) * 4), Abase + (size_t)(r * 256 + tid) * 4);
            CP16(smem_u32(dB + (r * 256 + tid) * 4), Bbase + (size_t)(r * 256 + tid) * 4);
        }
        asm volatile("cp.async.commit_group;");
    }
    int stage = 0;
    for (int c = 0; c < 8; c++) {
        if (c < 7) {
            float* dA = sm + (stage ^ 1) * 8192;
            float* dB = dA + 4096;
            const float* gA = Abase + (size_t)(c + 1) * 4096;
            const float* gB = Bbase + (size_t)(c + 1) * 4096;
#pragma unroll
            for (int r = 0; r < 4; r++) {
                CP16(smem_u32(dA + (r * 256 + tid) * 4), gA + (size_t)(r * 256 + tid) * 4);
                CP16(smem_u32(dB + (r * 256 + tid) * 4), gB + (size_t)(r * 256 + tid) * 4);
            }
            asm volatile("cp.async.commit_group;");
            asm volatile("cp.async.wait_group 1;");
        } else {
            asm volatile("cp.async.wait_group 0;");
        }
        __syncthreads();

        const float* A = sm + stage * 8192;
        const float* B = A + 4096;
#pragma unroll
        for (int kk = 0; kk < 4; kk++) {
            uint4 af[4];
            uint2 bf[4];
#pragma unroll
            for (int i = 0; i < 4; i++)
                af[i] = *(const uint4*)&A[(kk * 8 + wm * 4 + i) * 128 + lane * 4];
#pragma unroll
            for (int j = 0; j < 4; j++)
                bf[j] = *(const uint2*)&B[(kk * 16 + wn * 4 + j) * 64 + lane * 2];
#pragma unroll
            for (int i = 0; i < 4; i++)
#pragma unroll
                for (int j = 0; j < 4; j++) MMA_TF32V(acc[i][j], af[i], bf[j]);
        }
        __syncthreads();
        stage ^= 1;
    }

#pragma unroll
    for (int i = 0; i < 4; i++) {
#pragma unroll
        for (int j = 0; j < 4; j++) {
            int r = mblk * 128 + wm * 64 + i * 16 + quad;
            int cc = nblk * 128 + wn * 32 + j * 8 + qt * 2;
            *(float2*)&C[(size_t)r * ldc + cc] = make_float2(acc[i][j][0], acc[i][j][1]);
            *(float2*)&C[(size_t)(r + 8) * ldc + cc] = make_float2(acc[i][j][2], acc[i][j][3]);
        }
    }
}

// ---------------- band A, packed fragment order -----------------------------
__device__ __forceinline__ float cw_val(const float* wb, int t, int t0, int j)
{
    int s = t0 - 128 + j;
    int dlt = t - s;
    if (s < 0 || s >= TT || dlt >= WIN || dlt <= -WIN) return 0.f;
    return to_tf32(expf(wb[(size_t)t * TT + s]) - 1.f);
}

__global__ void build_cwP(const float* __restrict__ wb)
{
    int fid = blockIdx.x * 256 + threadIdx.x;
    int rg = fid >> 10;
    int q  = fid & 1023;
    int slot = q >> 5;
    int lane = q & 31;
    int tile = rg / 12, kc = rg - tile * 12;
    int kk = slot >> 3, mi = slot & 7;
    int quad = lane >> 2, qt = lane & 3;
    int t0 = tile * 128;
    int t = t0 + mi * 16 + quad;
    int j = kc * 32 + kk * 8 + qt;
    float4 v;
    v.x = cw_val(wb, t,     t0, j);
    v.y = cw_val(wb, t + 8, t0, j);
    v.z = cw_val(wb, t,     t0, j + 4);
    v.w = cw_val(wb, t + 8, t0, j + 4);
    *(float4*)&g_cwP[(size_t)fid * 4] = v;
}

__global__ void zero_uek_pad()
{
    size_t i = (size_t)blockIdx.x * 256 + threadIdx.x;
    size_t e = i * 4;
    int b = e / (384 * 512);
    int rem = e % (384 * 512);
    int r = rem / 512;
    int c = rem % 512;
    int p = (r < 128) ? r : (r + 2048);
    *(float4*)&g_uek[((size_t)b * PADT + p) * 512 + c] = make_float4(0.f, 0.f, 0.f, 0.f);
}

__global__ void reduce_final()
{
    int b = blockIdx.x;
    int i = threadIdx.x;
    float acc = 0.f;
    for (int j = 0; j < 32; j++)
        acc += g_Spart[((size_t)(b * 32 + j)) * 512 + i];
    g_S[(size_t)b * 512 + i] = acc;
}

// ---------------- band GEMM with fused gating + y-pack epilogue -------------
#define SPB 136
#define BSM_A 4096
#define BSM_B (32 * SPB)
#define BSTG (BSM_A + BSM_B)
#define BAND_SMEM (2 * BSTG * 4)

__global__ void __launch_bounds__(256, 2) band_gemm_f()
{
    extern __shared__ float bsm[];
    const int tid = threadIdx.x;
    const int nblk = blockIdx.x;     // 0..3
    const int tile = blockIdx.y;     // 0..15
    const int b    = blockIdx.z;
    const int t0 = tile * 128;
    const int n0 = nblk * 128;

    const float* Ap = g_cwP + (size_t)tile * 12 * 4096;
    const float* Bg = g_uek + (size_t)b * PADT * 512;

    const int lane = tid & 31, w = tid >> 5;
    const int wm = w & 1, wn = w >> 1;
    const int quad = lane >> 2, qt = lane & 3;
    const int brow = tid >> 3;
    const int bcol = (tid & 7) * 16;

    float acc[4][4][4];
#pragma unroll
    for (int i = 0; i < 4; i++)
#pragma unroll
        for (int j = 0; j < 4; j++)
#pragma unroll
            for (int e = 0; e < 4; e++) acc[i][j][e] = 0.f;

    auto issue = [&](int stg, int c) {
        float* sA = bsm + stg * BSTG;
        float* sB = sA + BSM_A;
        const float* gA = Ap + (size_t)c * 4096;
#pragma unroll
        for (int r = 0; r < 4; r++)
            CP16(smem_u32(sA + (r * 256 + tid) * 4), gA + (size_t)(r * 256 + tid) * 4);
        const float* bp = Bg + (size_t)(t0 + c * 32 + brow) * 512 + n0 + bcol;
        float* dst = sB + brow * SPB + bcol;
#pragma unroll
        for (int s = 0; s < 4; s++)
            CP16(smem_u32(dst + s * 4), bp + s * 4);
        asm volatile("cp.async.commit_group;");
    };

    issue(0, 0);
    int stage = 0;
    for (int c = 0; c < 12; c++) {
        if (c < 11) {
            issue(stage ^ 1, c + 1);
            asm volatile("cp.async.wait_group 1;");
        } else {
            asm volatile("cp.async.wait_group 0;");
        }
        __syncthreads();

        const float* A = bsm + stage * BSTG;
        const float* B = A + BSM_A;
        const int tbw = wm * 64;
#pragma unroll
        for (int kk = 0; kk < 4; kk++) {
            int jb = c * 32 + kk * 8;
            if (jb >= tbw - 6 && jb <= tbw + 318) {
                uint32_t b0[4], b1[4];
#pragma unroll
                for (int j = 0; j < 4; j++) {
                    int n = wn * 32 + j * 8 + quad;
                    b0[j] = *(const uint32_t*)&B[(kk * 8 + qt) * SPB + n];
                    b1[j] = *(const uint32_t*)&B[(kk * 8 + qt + 4) * SPB + n];
                }
#pragma unroll
                for (int i = 0; i < 4; i++) {
                    int tb = tbw + i * 16;
                    if (jb >= tb - 6 && jb <= tb + 270) {
                        uint4 af = *(const uint4*)&A[(kk * 8 + wm * 4 + i) * 128 + lane * 4];
#pragma unroll
                        for (int j = 0; j < 4; j++)
                            MMA_TF32S(acc[i][j], af, b0[j], b1[j]);
                    }
                }
            }
        }
        __syncthreads();
        stage ^= 1;
    }

    // fused epilogue: y = sigmoid(q) * (Su+num)/(Se+den), packed into g_yp
    const int mblk_y = b * 16 + tile;
#pragma unroll
    for (int i = 0; i < 4; i++) {
        int trow = t0 + wm * 64 + i * 16 + quad;
        size_t qrow = (size_t)(b * TT + trow) * 256;
        int mi = wm * 4 + i;
        float y0[4], y8[4];
#pragma unroll
        for (int j = 0; j < 4; j++) {
            int d = (n0 >> 1) + wn * 16 + j * 4 + qt;
            float2 S = *(const float2*)&g_S[(size_t)b * 512 + 2 * d];
            float q0 = g_q[qrow + d];
            float q8 = g_q[qrow + 8 * 256 + d];
            float sg0 = 1.f / (1.f + expf(-q0));
            float sg8 = 1.f / (1.f + expf(-q8));
            y0[j] = to_tf32(sg0 * (S.x + acc[i][j][0]) / (S.y + acc[i][j][1]));
            y8[j] = to_tf32(sg8 * (S.x + acc[i][j][2]) / (S.y + acc[i][j][3]));
        }
#pragma unroll
        for (int j0 = 0; j0 < 4; j0 += 2) {
            int c0 = (n0 >> 1) + wn * 16 + j0 * 4 + qt;
            int kc = c0 >> 5;
            int kk = (c0 >> 3) & 3;
            int slot = kk * 8 + mi;
            size_t off = (((size_t)(mblk_y * 8 + kc) * 32 + slot) * 32 + lane) * 4;
            *(float4*)&g_yp[off] = make_float4(y0[j0], y8[j0], y0[j0 + 1], y8[j0 + 1]);
        }
    }
}

// ---------------- launch ----------------------------------------------------
extern "C" void kernel_launch(void* const* d_in, const int* in_sizes, int n_in,
                              void* d_out, int out_size)
{
    const float* x      = (const float*)d_in[0];
    const float* Wq     = (const float*)d_in[1];
    const float* Wk     = (const float*)d_in[2];
    const float* Wv     = (const float*)d_in[3];
    const float* Wo     = (const float*)d_in[4];
    const float* w_bias = (const float*)d_in[5];
    float* out = (float*)d_out;

    float *yp, *wo;
    cudaGetSymbolAddress((void**)&yp, g_yp);
    cudaGetSymbolAddress((void**)&wo, g_wo);

    cudaFuncSetAttribute(gemm_qkv_h,
                         cudaFuncAttributeMaxDynamicSharedMemorySize, QH_SMEM);
    cudaFuncSetAttribute(gemm_tf32p,
                         cudaFuncAttributeMaxDynamicSharedMemorySize, PG_SMEM);
    cudaFuncSetAttribute(band_gemm_f,
                         cudaFuncAttributeMaxDynamicSharedMemorySize, BAND_SMEM);

    // preps (independent)
    pack_ah<<<4096, 256>>>(x);
    pack_wh<<<192, 256>>>(Wq, Wk, Wv);
    pack_wo<<<128, 256>>>(Wo);
    build_cwP<<<768, 256>>>(w_bias);
    zero_uek_pad<<<(BB * 384 * 512) / (256 * 4), 256>>>();

    // QKV projection (fp16 k16) + fused elementwise/uek/partial-sum epilogue
    gemm_qkv_h<<<dim3(6, BT / 128), 256, QH_SMEM>>>();

    // finish global sums
    reduce_final<<<BB, 512>>>();

    // band GEMM (tf32) + fused gating + fragment-packed y
    band_gemm_f<<<dim3(4, 16, BB), 256, BAND_SMEM>>>();

    // output projection: [32768,256] x [256,256] (tf32)
    gemm_tf32p<<<dim3(2, BT / 128), 256, PG_SMEM>>>(yp, wo, out, DD);
}